// round 9
// baseline (speedup 1.0000x reference)
#include <cuda_runtime.h>
#include <math.h>

#define Bsz  32
#define Tlen 512
#define Idim 1024
#define Hdim 1024
#define G4   4096
#define NBLK 128

// ---------------- device scratch ----------------
__device__ float g_xw[(size_t)Tlen * Bsz * G4];       // [t][b][4H]
__device__ float g_xr[(size_t)Bsz * Tlen * Idim];     // x pre-rounded to tf32
__device__ float g_wr[(size_t)G4 * Idim];             // W_ih pre-rounded to tf32
__device__ float g_hA[2][2][128][32][4];              // h in A-fragment layout (tf32 bits)
__device__ unsigned int g_bar;

// ---------------- helpers ----------------
__device__ __forceinline__ unsigned f2tf32(float f)
{
    unsigned r;
    asm("cvt.rna.tf32.f32 %0, %1;" : "=r"(r) : "f"(f));
    return r;
}
__device__ __forceinline__ void mma_tf32(float* d, const unsigned* a, const unsigned* b)
{
    asm volatile(
        "mma.sync.aligned.m16n8k8.row.col.f32.tf32.tf32.f32 "
        "{%0,%1,%2,%3},{%4,%5,%6,%7},{%8,%9},{%0,%1,%2,%3};"
        : "+f"(d[0]), "+f"(d[1]), "+f"(d[2]), "+f"(d[3])
        : "r"(a[0]), "r"(a[1]), "r"(a[2]), "r"(a[3]), "r"(b[0]), "r"(b[1]));
}
__device__ __forceinline__ void cp_async16(unsigned dst, const void* src)
{
    asm volatile("cp.async.cg.shared.global [%0], [%1], 16;" :: "r"(dst), "l"(src));
}
#define CP_COMMIT()  asm volatile("cp.async.commit_group;")
#define CP_WAIT(N)   asm volatile("cp.async.wait_group %0;" :: "n"(N))

__device__ __forceinline__ float sig_fast(float x)
{
    return __frcp_rn(1.f + __expf(-x));
}
__device__ __forceinline__ float tanh_fast(float x)
{
    return fmaf(2.f, __frcp_rn(1.f + __expf(-2.f * x)), -1.f);
}

// =======================================================================
// Kernel 0: pre-round x and W_ih to tf32 (RNA) -> unbiased GEMM inputs.
// =======================================================================
__global__ void __launch_bounds__(256) round_prep_kernel(
    const float* __restrict__ x, const float* __restrict__ Wih)
{
    if (blockIdx.x == 0 && threadIdx.x == 0) g_bar = 0u;
    const size_t NX = (size_t)Bsz * Tlen * Idim;   // 16M
    const size_t NW = (size_t)G4 * Idim;           // 4M
    size_t i0 = ((size_t)blockIdx.x * blockDim.x + threadIdx.x) * 4;
    size_t stride = (size_t)gridDim.x * blockDim.x * 4;
    for (size_t i = i0; i < NX; i += stride) {
        float4 v = *(const float4*)(x + i);
        uint4 r;
        r.x = f2tf32(v.x); r.y = f2tf32(v.y);
        r.z = f2tf32(v.z); r.w = f2tf32(v.w);
        *(uint4*)(g_xr + i) = r;
    }
    for (size_t i = i0; i < NW; i += stride) {
        float4 v = *(const float4*)(Wih + i);
        uint4 r;
        r.x = f2tf32(v.x); r.y = f2tf32(v.y);
        r.z = f2tf32(v.z); r.w = f2tf32(v.w);
        *(uint4*)(g_wr + i) = r;
    }
}

// =======================================================================
// Phase 1: g_xw = x @ Wih^T + b via tf32 mma.sync on pre-rounded inputs.
// CTA 128x128, BK=32, 256 thr (8 warps, 2Mx4N), 3-stage cp.async ring,
// one __syncthreads per k-chunk.
// =======================================================================
#define P1_PAD   36
#define P1_BUF   (128 * P1_PAD)
#define P1_STG   3
#define P1_SMEM  (2 * P1_STG * P1_BUF * 4)

__global__ void __launch_bounds__(256, 1) gemm_xw_kernel(const float* __restrict__ bias)
{
    extern __shared__ float sm[];
    float* Abuf = sm;                        // [3][128][36]
    float* Bbuf = sm + P1_STG * P1_BUF;      // [3][128][36]

    const int tid  = threadIdx.x;
    const int wi   = tid >> 5;
    const int lane = tid & 31;
    const int wm   = wi >> 2;            // 0..1
    const int wn   = wi & 3;             // 0..3
    const int g    = lane >> 2;
    const int tg   = lane & 3;

    const int bn = blockIdx.x * 128;
    const int bm = blockIdx.y * 128;

    const unsigned a_smb = (unsigned)__cvta_generic_to_shared(Abuf);
    const unsigned b_smb = (unsigned)__cvta_generic_to_shared(Bbuf);

    const int srow = tid >> 3;
    const int sseg = tid & 7;

    const float* Ag = g_xr + (size_t)(bm + srow) * Idim + sseg * 4;
    const float* Bg = g_wr + (size_t)(bn + srow) * Idim + sseg * 4;
    const unsigned sdoff = (unsigned)((srow * P1_PAD + sseg * 4) * 4);

    // prologue: stages 0,1
#pragma unroll
    for (int s = 0; s < 2; s++) {
        const int k0 = s * 32;
        unsigned bufo = (unsigned)(s * P1_BUF * 4);
#pragma unroll
        for (int p = 0; p < 4; p++) {
            unsigned d = sdoff + bufo + (unsigned)(p * 32 * P1_PAD * 4);
            cp_async16(a_smb + d, Ag + (size_t)p * 32 * Idim + k0);
            cp_async16(b_smb + d, Bg + (size_t)p * 32 * Idim + k0);
        }
        CP_COMMIT();
    }

    float D[4][4][4];
#pragma unroll
    for (int mi = 0; mi < 4; mi++)
#pragma unroll
        for (int ni = 0; ni < 4; ni++)
#pragma unroll
            for (int q = 0; q < 4; q++) D[mi][ni][q] = 0.f;

    int buf = 0;
    for (int kc = 0; kc < 32; kc++) {
        if (kc == 31) { CP_WAIT(0); } else { CP_WAIT(1); }
        __syncthreads();   // data visible; all warps done reading the buf being refilled

        if (kc + 2 < 32) {
            const int s  = (buf + 2) % P1_STG;
            const int k0 = (kc + 2) * 32;
            unsigned bufo = (unsigned)(s * P1_BUF * 4);
#pragma unroll
            for (int p = 0; p < 4; p++) {
                unsigned d = sdoff + bufo + (unsigned)(p * 32 * P1_PAD * 4);
                cp_async16(a_smb + d, Ag + (size_t)p * 32 * Idim + k0);
                cp_async16(b_smb + d, Bg + (size_t)p * 32 * Idim + k0);
            }
            CP_COMMIT();
        }

        const unsigned* Ab = (const unsigned*)(Abuf + buf * P1_BUF);
        const unsigned* Bb = (const unsigned*)(Bbuf + buf * P1_BUF);

#pragma unroll
        for (int k8 = 0; k8 < 4; k8++) {
            const int kc0 = k8 * 8;
            unsigned A[4][4], Bf[4][2];
#pragma unroll
            for (int mi = 0; mi < 4; mi++) {
                const unsigned* ap = Ab + (wm * 64 + mi * 16 + g) * P1_PAD + kc0 + tg;
                A[mi][0] = ap[0];
                A[mi][1] = ap[8 * P1_PAD];
                A[mi][2] = ap[4];
                A[mi][3] = ap[8 * P1_PAD + 4];
            }
#pragma unroll
            for (int ni = 0; ni < 4; ni++) {
                const unsigned* bp = Bb + (wn * 32 + ni * 8 + g) * P1_PAD + kc0 + tg;
                Bf[ni][0] = bp[0];
                Bf[ni][1] = bp[4];
            }
#pragma unroll
            for (int mi = 0; mi < 4; mi++)
#pragma unroll
                for (int ni = 0; ni < 4; ni++)
                    mma_tf32(D[mi][ni], A[mi], Bf[ni]);
        }

        buf = (buf + 1) % P1_STG;
    }

    // ---- epilogue ----
    float2 bv[4];
#pragma unroll
    for (int ni = 0; ni < 4; ni++) {
        int j0 = bn + wn * 32 + ni * 8 + tg * 2;
        bv[ni].x = __ldg(bias + j0);
        bv[ni].y = __ldg(bias + j0 + 1);
    }
#pragma unroll
    for (int mi = 0; mi < 4; mi++) {
        int r0 = bm + wm * 64 + mi * 16 + g;
        int r1 = r0 + 8;
        int t0 = r0 & (Tlen - 1), b0 = r0 >> 9;
        int t1 = r1 & (Tlen - 1), b1 = r1 >> 9;
        float* base0 = &g_xw[(size_t)t0 * (Bsz * G4) + (size_t)b0 * G4];
        float* base1 = &g_xw[(size_t)t1 * (Bsz * G4) + (size_t)b1 * G4];
#pragma unroll
        for (int ni = 0; ni < 4; ni++) {
            int j0 = bn + wn * 32 + ni * 8 + tg * 2;
            float2 v0; v0.x = D[mi][ni][0] + bv[ni].x; v0.y = D[mi][ni][1] + bv[ni].y;
            float2 v1; v1.x = D[mi][ni][2] + bv[ni].x; v1.y = D[mi][ni][3] + bv[ni].y;
            *(float2*)(base0 + j0) = v0;
            *(float2*)(base1 + j0) = v1;
        }
    }
}

// =======================================================================
// Phase 2: persistent tensor-core recurrence (UNCHANGED from best run).
// =======================================================================
#define SWB_FLOATS (4 * 128 * 32 * 2)           // 32768 (128 KB)
#define SPART_FLOATS (8 * 2 * 4 * 32 * 4)       // 4096  (16 KB)
#define SMEM_P2 ((SWB_FLOATS + SPART_FLOATS) * 4)

__device__ __forceinline__ void grid_barrier(unsigned target)
{
    __syncthreads();
    if (threadIdx.x == 0) {
        __threadfence();
        asm volatile("red.release.gpu.global.add.u32 [%0], %1;"
                     :: "l"(&g_bar), "r"(1u) : "memory");
        unsigned v;
        do {
            asm volatile("ld.acquire.gpu.global.u32 %0, [%1];"
                         : "=r"(v) : "l"(&g_bar) : "memory");
        } while (v < target);
    }
    __syncthreads();
}

__global__ void __launch_bounds__(256, 1) lstm_rec_kernel(
    const float* __restrict__ Whh, float* __restrict__ out)
{
    extern __shared__ float smem[];
    float* sWB   = smem;                 // [g][kt][lane][2] tf32 B fragments
    float* sPart = smem + SWB_FLOATS;    // [wi][mt][g][lane][4] fp32 partial D

    const int tid  = threadIdx.x;
    const int bid  = blockIdx.x;
    const int wi   = tid >> 5;
    const int lane = tid & 31;

    for (int idx = tid; idx < 4 * 128 * 32; idx += 256) {
        int l  = idx & 31;
        int kt = (idx >> 5) & 127;
        int g  = idx >> 12;
        int row = g * 1024 + bid * 8 + (l >> 2);
        int k0  = kt * 8 + (l & 3);
        unsigned* dst = (unsigned*)&sWB[((g * 128 + kt) * 32 + l) * 2];
        dst[0] = f2tf32(Whh[(size_t)row * Hdim + k0]);
        dst[1] = f2tf32(Whh[(size_t)row * Hdim + k0 + 4]);
    }

    const int rb = tid >> 3;
    const int rh = tid & 7;
    const int j  = bid * 8 + rh;

    const int p_mt   = rb >> 4;
    const int p_kt   = j >> 3;
    const int p_lane = (rb & 7) * 4 + (rh & 3);
    const int p_reg  = ((rb & 15) >> 3) + 2 * (rh >> 2);

    g_hA[0][p_mt][p_kt][p_lane][p_reg] = 0.f;

    const int laneD = (rb & 7) * 4 + (rh >> 1);
    const int regD  = (rh & 1) + 2 * ((rb & 15) >> 3);
    const int mtD   = rb >> 4;

    const float* xwp = g_xw + (size_t)rb * G4 + j;
    float xv[4];
#pragma unroll
    for (int g = 0; g < 4; g++) xv[g] = __ldg(xwp + g * 1024);

    float c_state = 0.f;
    unsigned target = NBLK;
    grid_barrier(target);

    const int kt0 = wi * 16;

    for (int t = 0; t < Tlen; t++) {
        const int rbuf = t & 1, wbuf = rbuf ^ 1;

        float D[2][4][4];
#pragma unroll
        for (int m = 0; m < 2; m++)
#pragma unroll
            for (int n = 0; n < 4; n++)
#pragma unroll
                for (int q = 0; q < 4; q++) D[m][n][q] = 0.f;

        uint4 A0 = __ldcg((const uint4*)&g_hA[rbuf][0][kt0][lane][0]);
        uint4 A1 = __ldcg((const uint4*)&g_hA[rbuf][1][kt0][lane][0]);
#pragma unroll
        for (int i = 0; i < 16; i++) {
            uint4 a0 = A0, a1 = A1;
            if (i < 15) {
                A0 = __ldcg((const uint4*)&g_hA[rbuf][0][kt0 + i + 1][lane][0]);
                A1 = __ldcg((const uint4*)&g_hA[rbuf][1][kt0 + i + 1][lane][0]);
            }
#pragma unroll
            for (int g = 0; g < 4; g++) {
                unsigned bfrag[2];
                *(uint2*)bfrag = *(const uint2*)&sWB[((g * 128 + kt0 + i) * 32 + lane) * 2];
                mma_tf32(D[0][g], (const unsigned*)&a0, bfrag);
                mma_tf32(D[1][g], (const unsigned*)&a1, bfrag);
            }
        }

#pragma unroll
        for (int m = 0; m < 2; m++)
#pragma unroll
            for (int g = 0; g < 4; g++)
                *(float4*)&sPart[(((wi * 2 + m) * 4 + g) * 32 + lane) * 4] =
                    *(float4*)D[m][g];
        __syncthreads();

        float z[4];
#pragma unroll
        for (int g = 0; g < 4; g++) {
            float s = xv[g];
#pragma unroll
            for (int w = 0; w < 8; w++)
                s += sPart[(((w * 2 + mtD) * 4 + g) * 32 + laneD) * 4 + regD];
            z[g] = s;
        }

        float ig = sig_fast(z[0]);
        float fg = sig_fast(z[1]);
        float gg = tanh_fast(z[2]);
        float og = sig_fast(z[3]);
        c_state = fmaf(fg, c_state, ig * gg);
        float hv = og * tanh_fast(c_state);

        *(unsigned*)&g_hA[wbuf][p_mt][p_kt][p_lane][p_reg] = f2tf32(hv);
        out[((size_t)rb * Tlen + t) * Hdim + j] = hv;

        if (t + 1 < Tlen) {
            const float* nx = xwp + (size_t)(t + 1) * (Bsz * G4);
#pragma unroll
            for (int g = 0; g < 4; g++) xv[g] = __ldg(nx + g * 1024);
        }

        target += NBLK;
        grid_barrier(target);
    }
}

// =======================================================================
extern "C" void kernel_launch(void* const* d_in, const int* in_sizes, int n_in,
                              void* d_out, int out_size)
{
    const float* x    = (const float*)d_in[0];
    const float* Wih  = (const float*)d_in[1];
    const float* Whh  = (const float*)d_in[2];
    const float* bias = (const float*)d_in[3];
    float* out = (float*)d_out;

    cudaFuncSetAttribute(gemm_xw_kernel,
                         cudaFuncAttributeMaxDynamicSharedMemorySize, P1_SMEM);
    cudaFuncSetAttribute(lstm_rec_kernel,
                         cudaFuncAttributeMaxDynamicSharedMemorySize, SMEM_P2);

    round_prep_kernel<<<1184, 256>>>(x, Wih);

    dim3 g1(G4 / 128, (Bsz * Tlen) / 128);   // (32, 128)
    gemm_xw_kernel<<<g1, 256, P1_SMEM>>>(bias);

    lstm_rec_kernel<<<NBLK, 256, SMEM_P2>>>(Whh, out);
}

// round 10
// speedup vs baseline: 1.0818x; 1.0818x over previous
#include <cuda_runtime.h>
#include <math.h>

#define Bsz  32
#define Tlen 512
#define Idim 1024
#define Hdim 1024
#define G4   4096
#define NBLK 128

// ---------------- device scratch ----------------
__device__ float g_xw[(size_t)Tlen * Bsz * G4];       // [t][b][4H]
// A in fragment-major order: [MT 1024][KT 128][lane 32] x float4
__device__ float4 g_xa[(size_t)1024 * 128 * 32];
// B (W_ih) fragment-major: [NT 512][KT2 64][lane 32] x float4
__device__ float4 g_wb[(size_t)512 * 64 * 32];
__device__ float g_hA[2][2][128][32][4];              // h A-frag layout (tf32 bits)
__device__ unsigned int g_bar;

// ---------------- helpers ----------------
__device__ __forceinline__ unsigned f2tf32(float f)
{
    unsigned r;
    asm("cvt.rna.tf32.f32 %0, %1;" : "=r"(r) : "f"(f));
    return r;
}
__device__ __forceinline__ void mma_tf32(float* d, const unsigned* a, const unsigned* b)
{
    asm volatile(
        "mma.sync.aligned.m16n8k8.row.col.f32.tf32.tf32.f32 "
        "{%0,%1,%2,%3},{%4,%5,%6,%7},{%8,%9},{%0,%1,%2,%3};"
        : "+f"(d[0]), "+f"(d[1]), "+f"(d[2]), "+f"(d[3])
        : "r"(a[0]), "r"(a[1]), "r"(a[2]), "r"(a[3]), "r"(b[0]), "r"(b[1]));
}
__device__ __forceinline__ void cp_async16(unsigned dst, const void* src)
{
    asm volatile("cp.async.cg.shared.global [%0], [%1], 16;" :: "r"(dst), "l"(src));
}
#define CP_COMMIT()  asm volatile("cp.async.commit_group;")
#define CP_WAIT(N)   asm volatile("cp.async.wait_group %0;" :: "n"(N))

__device__ __forceinline__ uint4 lds128(unsigned addr)
{
    uint4 v;
    asm volatile("ld.shared.v4.b32 {%0,%1,%2,%3}, [%4];"
                 : "=r"(v.x), "=r"(v.y), "=r"(v.z), "=r"(v.w) : "r"(addr));
    return v;
}
__device__ __forceinline__ float sig_fast(float x)
{
    return __frcp_rn(1.f + __expf(-x));
}
__device__ __forceinline__ float tanh_fast(float x)
{
    return fmaf(2.f, __frcp_rn(1.f + __expf(-2.f * x)), -1.f);
}

// =======================================================================
// Kernel 0: build fragment-major, tf32-rounded copies of x and W_ih.
// A frag (m16n8k8): lane l=g*4+tg holds {A[g][tg], A[g+8][tg],
//                                        A[g][tg+4], A[g+8][tg+4]}
// B frag pair (two k8): lane holds {B[g][tg], B[g][tg+4],
//                                   B[g][tg+8], B[g][tg+12]}
// =======================================================================
__global__ void __launch_bounds__(256) prep_kernel(
    const float* __restrict__ x, const float* __restrict__ Wih)
{
    if (blockIdx.x == 0 && threadIdx.x == 0) g_bar = 0u;
    const size_t NA = (size_t)1024 * 128 * 32;   // 4M items
    const size_t NW = (size_t)512 * 64 * 32;     // 1M items
    size_t i0 = (size_t)blockIdx.x * blockDim.x + threadIdx.x;
    size_t stride = (size_t)gridDim.x * blockDim.x;

    for (size_t i = i0; i < NA; i += stride) {
        int l  = (int)(i & 31);
        int KT = (int)((i >> 5) & 127);
        int MT = (int)(i >> 12);
        int g = l >> 2, tg = l & 3;
        const float* base = x + (size_t)(MT * 16 + g) * Idim + KT * 8 + tg;
        uint4 r;
        r.x = f2tf32(base[0]);
        r.y = f2tf32(base[8 * Idim]);
        r.z = f2tf32(base[4]);
        r.w = f2tf32(base[8 * Idim + 4]);
        *(uint4*)&g_xa[i] = r;
    }
    for (size_t i = i0; i < NW; i += stride) {
        int l   = (int)(i & 31);
        int KT2 = (int)((i >> 5) & 63);
        int NT  = (int)(i >> 11);
        int g = l >> 2, tg = l & 3;
        const float* base = Wih + (size_t)(NT * 8 + g) * Idim + KT2 * 16 + tg;
        uint4 r;
        r.x = f2tf32(base[0]);
        r.y = f2tf32(base[4]);
        r.z = f2tf32(base[8]);
        r.w = f2tf32(base[12]);
        *(uint4*)&g_wb[i] = r;
    }
}

// =======================================================================
// Phase 1: g_xw = x @ Wih^T + b. tf32 mma.sync on fragment-major inputs.
// CTA tile 128(M) x 64(N), BK=32, 256 thr (8 warps = 4M x 2N),
// warp tile 32x32. 3-stage cp.async ring, occupancy 2.
// smem per stage: A 8MT*4KT*32*16B = 16KB, B 8NT*2KT2*32*16B = 8KB.
// =======================================================================
#define P1_STG    3
#define P1_ABYTES (8 * 4 * 32 * 16)     // 16384
#define P1_BBYTES (8 * 2 * 32 * 16)     // 8192
#define P1_SMEM   (P1_STG * (P1_ABYTES + P1_BBYTES))

__global__ void __launch_bounds__(256, 2) gemm_xw_kernel(const float* __restrict__ bias)
{
    extern __shared__ float sm[];

    const int tid  = threadIdx.x;
    const int wi   = tid >> 5;
    const int lane = tid & 31;
    const int wm   = wi >> 1;            // 0..3
    const int wn   = wi & 1;             // 0..1
    const int g    = lane >> 2;
    const int tg   = lane & 3;

    const int bn  = blockIdx.x * 64;
    const int bm  = blockIdx.y * 128;
    const int MT0 = blockIdx.y * 8;
    const int NT0 = blockIdx.x * 8;

    const unsigned smb = (unsigned)__cvta_generic_to_shared(sm);
    // stage s: A at smb + s*(A+B), B at smb + s*(A+B) + A

    // staging assignments
    // A: 1024 float4 per kc -> tid + j*256, j 0..3
    // B: 512  float4 per kc -> tid + j*256, j 0..1

    float D[2][4][4];
#pragma unroll
    for (int mi = 0; mi < 2; mi++)
#pragma unroll
        for (int ni = 0; ni < 4; ni++)
#pragma unroll
            for (int q = 0; q < 4; q++) D[mi][ni][q] = 0.f;

    // ---- prologue: stages for kc=0,1 ----
#pragma unroll
    for (int s = 0; s < 2; s++) {
        const unsigned sb = smb + (unsigned)(s * (P1_ABYTES + P1_BBYTES));
#pragma unroll
        for (int j = 0; j < 4; j++) {
            int item = tid + j * 256;            // (mt*4+kt)*32 + l
            int mt = item >> 7, kt = (item >> 5) & 3, l = item & 31;
            const float4* src = g_xa + ((size_t)(MT0 + mt) * 128 + s * 4 + kt) * 32 + l;
            cp_async16(sb + (unsigned)(item * 16), src);
        }
#pragma unroll
        for (int j = 0; j < 2; j++) {
            int item = tid + j * 256;            // (nt*2+kt2)*32 + l
            int nt = item >> 6, kt2 = (item >> 5) & 1, l = item & 31;
            const float4* src = g_wb + ((size_t)(NT0 + nt) * 64 + s * 2 + kt2) * 32 + l;
            cp_async16(sb + (unsigned)(P1_ABYTES + item * 16), src);
        }
        CP_COMMIT();
    }

    int buf = 0;
    for (int kc = 0; kc < 32; kc++) {
        if (kc == 31) { CP_WAIT(0); } else { CP_WAIT(1); }
        __syncthreads();

        if (kc + 2 < 32) {
            const int s = (buf + 2) % P1_STG;
            const unsigned sb = smb + (unsigned)(s * (P1_ABYTES + P1_BBYTES));
#pragma unroll
            for (int j = 0; j < 4; j++) {
                int item = tid + j * 256;
                int mt = item >> 7, kt = (item >> 5) & 3, l = item & 31;
                const float4* src =
                    g_xa + ((size_t)(MT0 + mt) * 128 + (kc + 2) * 4 + kt) * 32 + l;
                cp_async16(sb + (unsigned)(item * 16), src);
            }
#pragma unroll
            for (int j = 0; j < 2; j++) {
                int item = tid + j * 256;
                int nt = item >> 6, kt2 = (item >> 5) & 1, l = item & 31;
                const float4* src =
                    g_wb + ((size_t)(NT0 + nt) * 64 + (kc + 2) * 2 + kt2) * 32 + l;
                cp_async16(sb + (unsigned)(P1_BBYTES * 0 + P1_ABYTES + item * 16), src);
            }
            CP_COMMIT();
        }

        const unsigned Ab = smb + (unsigned)(buf * (P1_ABYTES + P1_BBYTES));
        const unsigned Bb = Ab + (unsigned)P1_ABYTES;

#pragma unroll
        for (int kt2 = 0; kt2 < 2; kt2++) {
            uint4 Bp[4];
#pragma unroll
            for (int ni = 0; ni < 4; ni++)
                Bp[ni] = lds128(Bb +
                    (unsigned)((((wn * 4 + ni) * 2 + kt2) * 32 + lane) * 16));
#pragma unroll
            for (int half = 0; half < 2; half++) {
                const int k8 = kt2 * 2 + half;
                uint4 Aq[2];
#pragma unroll
                for (int mi = 0; mi < 2; mi++)
                    Aq[mi] = lds128(Ab +
                        (unsigned)((((wm * 2 + mi) * 4 + k8) * 32 + lane) * 16));
#pragma unroll
                for (int mi = 0; mi < 2; mi++)
#pragma unroll
                    for (int ni = 0; ni < 4; ni++) {
                        unsigned bfrag[2];
                        bfrag[0] = half ? Bp[ni].z : Bp[ni].x;
                        bfrag[1] = half ? Bp[ni].w : Bp[ni].y;
                        mma_tf32(D[mi][ni], (const unsigned*)&Aq[mi], bfrag);
                    }
            }
        }

        buf = (buf + 1) % P1_STG;
    }

    // ---- epilogue: +bias, scatter to g_xw[t][b][n] ----
    float2 bv[4];
#pragma unroll
    for (int ni = 0; ni < 4; ni++) {
        int j0 = bn + wn * 32 + ni * 8 + tg * 2;
        bv[ni].x = __ldg(bias + j0);
        bv[ni].y = __ldg(bias + j0 + 1);
    }
#pragma unroll
    for (int mi = 0; mi < 2; mi++) {
        int r0 = bm + wm * 32 + mi * 16 + g;
        int r1 = r0 + 8;
        int t0 = r0 & (Tlen - 1), b0 = r0 >> 9;
        int t1 = r1 & (Tlen - 1), b1 = r1 >> 9;
        float* base0 = &g_xw[(size_t)t0 * (Bsz * G4) + (size_t)b0 * G4];
        float* base1 = &g_xw[(size_t)t1 * (Bsz * G4) + (size_t)b1 * G4];
#pragma unroll
        for (int ni = 0; ni < 4; ni++) {
            int j0 = bn + wn * 32 + ni * 8 + tg * 2;
            float2 v0; v0.x = D[mi][ni][0] + bv[ni].x; v0.y = D[mi][ni][1] + bv[ni].y;
            float2 v1; v1.x = D[mi][ni][2] + bv[ni].x; v1.y = D[mi][ni][3] + bv[ni].y;
            *(float2*)(base0 + j0) = v0;
            *(float2*)(base1 + j0) = v1;
        }
    }
}

// =======================================================================
// Phase 2: persistent tensor-core recurrence (UNCHANGED from best run).
// =======================================================================
#define SWB_FLOATS (4 * 128 * 32 * 2)           // 32768 (128 KB)
#define SPART_FLOATS (8 * 2 * 4 * 32 * 4)       // 4096  (16 KB)
#define SMEM_P2 ((SWB_FLOATS + SPART_FLOATS) * 4)

__device__ __forceinline__ void grid_barrier(unsigned target)
{
    __syncthreads();
    if (threadIdx.x == 0) {
        __threadfence();
        asm volatile("red.release.gpu.global.add.u32 [%0], %1;"
                     :: "l"(&g_bar), "r"(1u) : "memory");
        unsigned v;
        do {
            asm volatile("ld.acquire.gpu.global.u32 %0, [%1];"
                         : "=r"(v) : "l"(&g_bar) : "memory");
        } while (v < target);
    }
    __syncthreads();
}

__global__ void __launch_bounds__(256, 1) lstm_rec_kernel(
    const float* __restrict__ Whh, float* __restrict__ out)
{
    extern __shared__ float smem[];
    float* sWB   = smem;                 // [g][kt][lane][2] tf32 B fragments
    float* sPart = smem + SWB_FLOATS;    // [wi][mt][g][lane][4] fp32 partial D

    const int tid  = threadIdx.x;
    const int bid  = blockIdx.x;
    const int wi   = tid >> 5;
    const int lane = tid & 31;

    for (int idx = tid; idx < 4 * 128 * 32; idx += 256) {
        int l  = idx & 31;
        int kt = (idx >> 5) & 127;
        int g  = idx >> 12;
        int row = g * 1024 + bid * 8 + (l >> 2);
        int k0  = kt * 8 + (l & 3);
        unsigned* dst = (unsigned*)&sWB[((g * 128 + kt) * 32 + l) * 2];
        dst[0] = f2tf32(Whh[(size_t)row * Hdim + k0]);
        dst[1] = f2tf32(Whh[(size_t)row * Hdim + k0 + 4]);
    }

    const int rb = tid >> 3;
    const int rh = tid & 7;
    const int j  = bid * 8 + rh;

    const int p_mt   = rb >> 4;
    const int p_kt   = j >> 3;
    const int p_lane = (rb & 7) * 4 + (rh & 3);
    const int p_reg  = ((rb & 15) >> 3) + 2 * (rh >> 2);

    g_hA[0][p_mt][p_kt][p_lane][p_reg] = 0.f;

    const int laneD = (rb & 7) * 4 + (rh >> 1);
    const int regD  = (rh & 1) + 2 * ((rb & 15) >> 3);
    const int mtD   = rb >> 4;

    const float* xwp = g_xw + (size_t)rb * G4 + j;
    float xv[4];
#pragma unroll
    for (int g = 0; g < 4; g++) xv[g] = __ldg(xwp + g * 1024);

    float c_state = 0.f;
    unsigned target = NBLK;
    grid_barrier(target);

    const int kt0 = wi * 16;

    for (int t = 0; t < Tlen; t++) {
        const int rbuf = t & 1, wbuf = rbuf ^ 1;

        float D[2][4][4];
#pragma unroll
        for (int m = 0; m < 2; m++)
#pragma unroll
            for (int n = 0; n < 4; n++)
#pragma unroll
                for (int q = 0; q < 4; q++) D[m][n][q] = 0.f;

        uint4 A0 = __ldcg((const uint4*)&g_hA[rbuf][0][kt0][lane][0]);
        uint4 A1 = __ldcg((const uint4*)&g_hA[rbuf][1][kt0][lane][0]);
#pragma unroll
        for (int i = 0; i < 16; i++) {
            uint4 a0 = A0, a1 = A1;
            if (i < 15) {
                A0 = __ldcg((const uint4*)&g_hA[rbuf][0][kt0 + i + 1][lane][0]);
                A1 = __ldcg((const uint4*)&g_hA[rbuf][1][kt0 + i + 1][lane][0]);
            }
#pragma unroll
            for (int g = 0; g < 4; g++) {
                unsigned bfrag[2];
                *(uint2*)bfrag = *(const uint2*)&sWB[((g * 128 + kt0 + i) * 32 + lane) * 2];
                mma_tf32(D[0][g], (const unsigned*)&a0, bfrag);
                mma_tf32(D[1][g], (const unsigned*)&a1, bfrag);
            }
        }

#pragma unroll
        for (int m = 0; m < 2; m++)
#pragma unroll
            for (int g = 0; g < 4; g++)
                *(float4*)&sPart[(((wi * 2 + m) * 4 + g) * 32 + lane) * 4] =
                    *(float4*)D[m][g];
        __syncthreads();

        float z[4];
#pragma unroll
        for (int g = 0; g < 4; g++) {
            float s = xv[g];
#pragma unroll
            for (int w = 0; w < 8; w++)
                s += sPart[(((w * 2 + mtD) * 4 + g) * 32 + laneD) * 4 + regD];
            z[g] = s;
        }

        float ig = sig_fast(z[0]);
        float fg = sig_fast(z[1]);
        float gg = tanh_fast(z[2]);
        float og = sig_fast(z[3]);
        c_state = fmaf(fg, c_state, ig * gg);
        float hv = og * tanh_fast(c_state);

        *(unsigned*)&g_hA[wbuf][p_mt][p_kt][p_lane][p_reg] = f2tf32(hv);
        out[((size_t)rb * Tlen + t) * Hdim + j] = hv;

        if (t + 1 < Tlen) {
            const float* nx = xwp + (size_t)(t + 1) * (Bsz * G4);
#pragma unroll
            for (int g = 0; g < 4; g++) xv[g] = __ldg(nx + g * 1024);
        }

        target += NBLK;
        grid_barrier(target);
    }
}

// =======================================================================
extern "C" void kernel_launch(void* const* d_in, const int* in_sizes, int n_in,
                              void* d_out, int out_size)
{
    const float* x    = (const float*)d_in[0];
    const float* Wih  = (const float*)d_in[1];
    const float* Whh  = (const float*)d_in[2];
    const float* bias = (const float*)d_in[3];
    float* out = (float*)d_out;

    cudaFuncSetAttribute(gemm_xw_kernel,
                         cudaFuncAttributeMaxDynamicSharedMemorySize, P1_SMEM);
    cudaFuncSetAttribute(lstm_rec_kernel,
                         cudaFuncAttributeMaxDynamicSharedMemorySize, SMEM_P2);

    prep_kernel<<<2048, 256>>>(x, Wih);

    dim3 g1(G4 / 64, (Bsz * Tlen) / 128);   // (64, 128)
    gemm_xw_kernel<<<g1, 256, P1_SMEM>>>(bias);

    lstm_rec_kernel<<<NBLK, 256, SMEM_P2>>>(Whh, out);
}

// round 11
// speedup vs baseline: 1.1040x; 1.0206x over previous
#include <cuda_runtime.h>
#include <math.h>

#define Bsz  32
#define Tlen 512
#define Idim 1024
#define Hdim 1024
#define G4   4096
#define NBLK 128

// ---------------- device scratch ----------------
__device__ float g_xw[(size_t)Tlen * Bsz * G4];       // [t][b][4H]
// A fragment-major: [MT 1024][KT 128][lane 32] x float4
__device__ float4 g_xa[(size_t)1024 * 128 * 32];
// B (W_ih) fragment-major: [NT 512][KT2 64][lane 32] x float4
__device__ float4 g_wb[(size_t)512 * 64 * 32];
__device__ float g_hA[2][2][128][32][4];              // h A-frag layout (tf32 bits)
__device__ unsigned int g_bar;

// ---------------- helpers ----------------
__device__ __forceinline__ unsigned f2tf32(float f)
{
    unsigned r;
    asm("cvt.rna.tf32.f32 %0, %1;" : "=r"(r) : "f"(f));
    return r;
}
__device__ __forceinline__ void mma_tf32(float* d, const unsigned* a, const unsigned* b)
{
    asm volatile(
        "mma.sync.aligned.m16n8k8.row.col.f32.tf32.tf32.f32 "
        "{%0,%1,%2,%3},{%4,%5,%6,%7},{%8,%9},{%0,%1,%2,%3};"
        : "+f"(d[0]), "+f"(d[1]), "+f"(d[2]), "+f"(d[3])
        : "r"(a[0]), "r"(a[1]), "r"(a[2]), "r"(a[3]), "r"(b[0]), "r"(b[1]));
}
__device__ __forceinline__ void cp_async16(unsigned dst, const void* src)
{
    asm volatile("cp.async.cg.shared.global [%0], [%1], 16;" :: "r"(dst), "l"(src));
}
#define CP_COMMIT()  asm volatile("cp.async.commit_group;")
#define CP_WAIT(N)   asm volatile("cp.async.wait_group %0;" :: "n"(N))

__device__ __forceinline__ uint4 lds128(unsigned addr)
{
    uint4 v;
    asm volatile("ld.shared.v4.b32 {%0,%1,%2,%3}, [%4];"
                 : "=r"(v.x), "=r"(v.y), "=r"(v.z), "=r"(v.w) : "r"(addr));
    return v;
}
__device__ __forceinline__ float sig_fast(float x)
{
    return __frcp_rn(1.f + __expf(-x));
}
__device__ __forceinline__ float tanh_fast(float x)
{
    return fmaf(2.f, __frcp_rn(1.f + __expf(-2.f * x)), -1.f);
}

// =======================================================================
// Kernel 0: build fragment-major tf32-rounded copies of x and W_ih.
// =======================================================================
__global__ void __launch_bounds__(256) prep_kernel(
    const float* __restrict__ x, const float* __restrict__ Wih)
{
    if (blockIdx.x == 0 && threadIdx.x == 0) g_bar = 0u;
    const size_t NA = (size_t)1024 * 128 * 32;
    const size_t NW = (size_t)512 * 64 * 32;
    size_t i0 = (size_t)blockIdx.x * blockDim.x + threadIdx.x;
    size_t stride = (size_t)gridDim.x * blockDim.x;

    for (size_t i = i0; i < NA; i += stride) {
        int l  = (int)(i & 31);
        int KT = (int)((i >> 5) & 127);
        int MT = (int)(i >> 12);
        int g = l >> 2, tg = l & 3;
        const float* base = x + (size_t)(MT * 16 + g) * Idim + KT * 8 + tg;
        uint4 r;
        r.x = f2tf32(base[0]);
        r.y = f2tf32(base[8 * Idim]);
        r.z = f2tf32(base[4]);
        r.w = f2tf32(base[8 * Idim + 4]);
        *(uint4*)&g_xa[i] = r;
    }
    for (size_t i = i0; i < NW; i += stride) {
        int l   = (int)(i & 31);
        int KT2 = (int)((i >> 5) & 63);
        int NT  = (int)(i >> 11);
        int g = l >> 2, tg = l & 3;
        const float* base = Wih + (size_t)(NT * 8 + g) * Idim + KT2 * 16 + tg;
        uint4 r;
        r.x = f2tf32(base[0]);
        r.y = f2tf32(base[4]);
        r.z = f2tf32(base[8]);
        r.w = f2tf32(base[12]);
        *(uint4*)&g_wb[i] = r;
    }
}

// =======================================================================
// Phase 1: g_xw = x @ Wih^T + b. tf32 mma.sync, fragment-major inputs.
// CTA tile 128(M) x 128(N), BK=32, 256 thr (8 warps = 2M x 4N),
// warp tile 64x32. 3-stage cp.async ring, occupancy 2.
// smem/stage: A 8MT*4KT*32*16B = 16KB, B 16NT*2KT2*32*16B = 16KB.
// =======================================================================
#define P1_STG    3
#define P1_ABYTES (8 * 4 * 32 * 16)      // 16384
#define P1_BBYTES (16 * 2 * 32 * 16)     // 16384
#define P1_STRIDE (P1_ABYTES + P1_BBYTES)
#define P1_SMEM   (P1_STG * P1_STRIDE)   // 98304

__global__ void __launch_bounds__(256, 2) gemm_xw_kernel(const float* __restrict__ bias)
{
    extern __shared__ float sm[];

    const int tid  = threadIdx.x;
    const int wi   = tid >> 5;
    const int lane = tid & 31;
    const int wm   = wi >> 2;            // 0..1
    const int wn   = wi & 3;             // 0..3
    const int g    = lane >> 2;
    const int tg   = lane & 3;

    const int bn  = blockIdx.x * 128;
    const int bm  = blockIdx.y * 128;
    const int MT0 = blockIdx.y * 8;
    const int NT0 = blockIdx.x * 16;

    const unsigned smb = (unsigned)__cvta_generic_to_shared(sm);

    float D[4][4][4];
#pragma unroll
    for (int mi = 0; mi < 4; mi++)
#pragma unroll
        for (int ni = 0; ni < 4; ni++)
#pragma unroll
            for (int q = 0; q < 4; q++) D[mi][ni][q] = 0.f;

    // ---- prologue: stage kc=0,1 ----
#pragma unroll
    for (int s = 0; s < 2; s++) {
        const unsigned sb = smb + (unsigned)(s * P1_STRIDE);
#pragma unroll
        for (int j = 0; j < 4; j++) {
            int item = tid + j * 256;            // (mt*4+kt)*32 + l
            int mt = item >> 7, kt = (item >> 5) & 3, l = item & 31;
            const float4* src = g_xa + ((size_t)(MT0 + mt) * 128 + s * 4 + kt) * 32 + l;
            cp_async16(sb + (unsigned)(item * 16), src);
        }
#pragma unroll
        for (int j = 0; j < 4; j++) {
            int item = tid + j * 256;            // (nt*2+kt2)*32 + l
            int nt = item >> 6, kt2 = (item >> 5) & 1, l = item & 31;
            const float4* src = g_wb + ((size_t)(NT0 + nt) * 64 + s * 2 + kt2) * 32 + l;
            cp_async16(sb + (unsigned)(P1_ABYTES + item * 16), src);
        }
        CP_COMMIT();
    }

    int buf = 0;
    for (int kc = 0; kc < 32; kc++) {
        if (kc == 31) { CP_WAIT(0); } else { CP_WAIT(1); }
        __syncthreads();

        if (kc + 2 < 32) {
            const int s = (buf + 2) % P1_STG;
            const unsigned sb = smb + (unsigned)(s * P1_STRIDE);
#pragma unroll
            for (int j = 0; j < 4; j++) {
                int item = tid + j * 256;
                int mt = item >> 7, kt = (item >> 5) & 3, l = item & 31;
                const float4* src =
                    g_xa + ((size_t)(MT0 + mt) * 128 + (kc + 2) * 4 + kt) * 32 + l;
                cp_async16(sb + (unsigned)(item * 16), src);
            }
#pragma unroll
            for (int j = 0; j < 4; j++) {
                int item = tid + j * 256;
                int nt = item >> 6, kt2 = (item >> 5) & 1, l = item & 31;
                const float4* src =
                    g_wb + ((size_t)(NT0 + nt) * 64 + (kc + 2) * 2 + kt2) * 32 + l;
                cp_async16(sb + (unsigned)(P1_ABYTES + item * 16), src);
            }
            CP_COMMIT();
        }

        const unsigned Ab = smb + (unsigned)(buf * P1_STRIDE);
        const unsigned Bb = Ab + (unsigned)P1_ABYTES;

#pragma unroll
        for (int kt2 = 0; kt2 < 2; kt2++) {
            uint4 Bp[4];
#pragma unroll
            for (int ni = 0; ni < 4; ni++)
                Bp[ni] = lds128(Bb +
                    (unsigned)((((wn * 4 + ni) * 2 + kt2) * 32 + lane) * 16));
#pragma unroll
            for (int half = 0; half < 2; half++) {
                const int k8 = kt2 * 2 + half;
                uint4 Aq[4];
#pragma unroll
                for (int mi = 0; mi < 4; mi++)
                    Aq[mi] = lds128(Ab +
                        (unsigned)((((wm * 4 + mi) * 4 + k8) * 32 + lane) * 16));
#pragma unroll
                for (int mi = 0; mi < 4; mi++)
#pragma unroll
                    for (int ni = 0; ni < 4; ni++) {
                        unsigned bfrag[2];
                        bfrag[0] = half ? Bp[ni].z : Bp[ni].x;
                        bfrag[1] = half ? Bp[ni].w : Bp[ni].y;
                        mma_tf32(D[mi][ni], (const unsigned*)&Aq[mi], bfrag);
                    }
            }
        }

        buf = (buf + 1) % P1_STG;
    }

    // ---- epilogue: +bias, scatter to g_xw[t][b][n] ----
    float2 bv[4];
#pragma unroll
    for (int ni = 0; ni < 4; ni++) {
        int j0 = bn + (wn * 4 + ni) * 8 + tg * 2;
        bv[ni].x = __ldg(bias + j0);
        bv[ni].y = __ldg(bias + j0 + 1);
    }
#pragma unroll
    for (int mi = 0; mi < 4; mi++) {
        int r0 = bm + wm * 64 + mi * 16 + g;
        int r1 = r0 + 8;
        int t0 = r0 & (Tlen - 1), b0 = r0 >> 9;
        int t1 = r1 & (Tlen - 1), b1 = r1 >> 9;
        float* base0 = &g_xw[(size_t)t0 * (Bsz * G4) + (size_t)b0 * G4];
        float* base1 = &g_xw[(size_t)t1 * (Bsz * G4) + (size_t)b1 * G4];
#pragma unroll
        for (int ni = 0; ni < 4; ni++) {
            int j0 = bn + (wn * 4 + ni) * 8 + tg * 2;
            float2 v0; v0.x = D[mi][ni][0] + bv[ni].x; v0.y = D[mi][ni][1] + bv[ni].y;
            float2 v1; v1.x = D[mi][ni][2] + bv[ni].x; v1.y = D[mi][ni][3] + bv[ni].y;
            *(float2*)(base0 + j0) = v0;
            *(float2*)(base1 + j0) = v1;
        }
    }
}

// =======================================================================
// Phase 2: persistent tensor-core recurrence (UNCHANGED — at its floor).
// =======================================================================
#define SWB_FLOATS (4 * 128 * 32 * 2)           // 32768 (128 KB)
#define SPART_FLOATS (8 * 2 * 4 * 32 * 4)       // 4096  (16 KB)
#define SMEM_P2 ((SWB_FLOATS + SPART_FLOATS) * 4)

__device__ __forceinline__ void grid_barrier(unsigned target)
{
    __syncthreads();
    if (threadIdx.x == 0) {
        __threadfence();
        asm volatile("red.release.gpu.global.add.u32 [%0], %1;"
                     :: "l"(&g_bar), "r"(1u) : "memory");
        unsigned v;
        do {
            asm volatile("ld.acquire.gpu.global.u32 %0, [%1];"
                         : "=r"(v) : "l"(&g_bar) : "memory");
        } while (v < target);
    }
    __syncthreads();
}

__global__ void __launch_bounds__(256, 1) lstm_rec_kernel(
    const float* __restrict__ Whh, float* __restrict__ out)
{
    extern __shared__ float smem[];
    float* sWB   = smem;                 // [g][kt][lane][2] tf32 B fragments
    float* sPart = smem + SWB_FLOATS;    // [wi][mt][g][lane][4] fp32 partial D

    const int tid  = threadIdx.x;
    const int bid  = blockIdx.x;
    const int wi   = tid >> 5;
    const int lane = tid & 31;

    for (int idx = tid; idx < 4 * 128 * 32; idx += 256) {
        int l  = idx & 31;
        int kt = (idx >> 5) & 127;
        int g  = idx >> 12;
        int row = g * 1024 + bid * 8 + (l >> 2);
        int k0  = kt * 8 + (l & 3);
        unsigned* dst = (unsigned*)&sWB[((g * 128 + kt) * 32 + l) * 2];
        dst[0] = f2tf32(Whh[(size_t)row * Hdim + k0]);
        dst[1] = f2tf32(Whh[(size_t)row * Hdim + k0 + 4]);
    }

    const int rb = tid >> 3;
    const int rh = tid & 7;
    const int j  = bid * 8 + rh;

    const int p_mt   = rb >> 4;
    const int p_kt   = j >> 3;
    const int p_lane = (rb & 7) * 4 + (rh & 3);
    const int p_reg  = ((rb & 15) >> 3) + 2 * (rh >> 2);

    g_hA[0][p_mt][p_kt][p_lane][p_reg] = 0.f;

    const int laneD = (rb & 7) * 4 + (rh >> 1);
    const int regD  = (rh & 1) + 2 * ((rb & 15) >> 3);
    const int mtD   = rb >> 4;

    const float* xwp = g_xw + (size_t)rb * G4 + j;
    float xv[4];
#pragma unroll
    for (int g = 0; g < 4; g++) xv[g] = __ldg(xwp + g * 1024);

    float c_state = 0.f;
    unsigned target = NBLK;
    grid_barrier(target);

    const int kt0 = wi * 16;

    for (int t = 0; t < Tlen; t++) {
        const int rbuf = t & 1, wbuf = rbuf ^ 1;

        float D[2][4][4];
#pragma unroll
        for (int m = 0; m < 2; m++)
#pragma unroll
            for (int n = 0; n < 4; n++)
#pragma unroll
                for (int q = 0; q < 4; q++) D[m][n][q] = 0.f;

        uint4 A0 = __ldcg((const uint4*)&g_hA[rbuf][0][kt0][lane][0]);
        uint4 A1 = __ldcg((const uint4*)&g_hA[rbuf][1][kt0][lane][0]);
#pragma unroll
        for (int i = 0; i < 16; i++) {
            uint4 a0 = A0, a1 = A1;
            if (i < 15) {
                A0 = __ldcg((const uint4*)&g_hA[rbuf][0][kt0 + i + 1][lane][0]);
                A1 = __ldcg((const uint4*)&g_hA[rbuf][1][kt0 + i + 1][lane][0]);
            }
#pragma unroll
            for (int g = 0; g < 4; g++) {
                unsigned bfrag[2];
                *(uint2*)bfrag = *(const uint2*)&sWB[((g * 128 + kt0 + i) * 32 + lane) * 2];
                mma_tf32(D[0][g], (const unsigned*)&a0, bfrag);
                mma_tf32(D[1][g], (const unsigned*)&a1, bfrag);
            }
        }

#pragma unroll
        for (int m = 0; m < 2; m++)
#pragma unroll
            for (int g = 0; g < 4; g++)
                *(float4*)&sPart[(((wi * 2 + m) * 4 + g) * 32 + lane) * 4] =
                    *(float4*)D[m][g];
        __syncthreads();

        float z[4];
#pragma unroll
        for (int g = 0; g < 4; g++) {
            float s = xv[g];
#pragma unroll
            for (int w = 0; w < 8; w++)
                s += sPart[(((w * 2 + mtD) * 4 + g) * 32 + laneD) * 4 + regD];
            z[g] = s;
        }

        float ig = sig_fast(z[0]);
        float fg = sig_fast(z[1]);
        float gg = tanh_fast(z[2]);
        float og = sig_fast(z[3]);
        c_state = fmaf(fg, c_state, ig * gg);
        float hv = og * tanh_fast(c_state);

        *(unsigned*)&g_hA[wbuf][p_mt][p_kt][p_lane][p_reg] = f2tf32(hv);
        out[((size_t)rb * Tlen + t) * Hdim + j] = hv;

        if (t + 1 < Tlen) {
            const float* nx = xwp + (size_t)(t + 1) * (Bsz * G4);
#pragma unroll
            for (int g = 0; g < 4; g++) xv[g] = __ldg(nx + g * 1024);
        }

        target += NBLK;
        grid_barrier(target);
    }
}

// =======================================================================
extern "C" void kernel_launch(void* const* d_in, const int* in_sizes, int n_in,
                              void* d_out, int out_size)
{
    const float* x    = (const float*)d_in[0];
    const float* Wih  = (const float*)d_in[1];
    const float* Whh  = (const float*)d_in[2];
    const float* bias = (const float*)d_in[3];
    float* out = (float*)d_out;

    cudaFuncSetAttribute(gemm_xw_kernel,
                         cudaFuncAttributeMaxDynamicSharedMemorySize, P1_SMEM);
    cudaFuncSetAttribute(lstm_rec_kernel,
                         cudaFuncAttributeMaxDynamicSharedMemorySize, SMEM_P2);

    prep_kernel<<<2048, 256>>>(x, Wih);

    dim3 g1(G4 / 128, (Bsz * Tlen) / 128);   // (32, 128)
    gemm_xw_kernel<<<g1, 256, P1_SMEM>>>(bias);

    lstm_rec_kernel<<<NBLK, 256, SMEM_P2>>>(Whh, out);
}